// round 13
// baseline (speedup 1.0000x reference)
#include <cuda_runtime.h>
#include <cuda_fp16.h>
#include <math_constants.h>
#include <cstdint>

// Problem-fixed maxima (DGCNN: N=50000 nodes, E=1000000 edges, max width 512)
#define NMAX 50000
#define EMAX 1000000

// Scratch (static __device__ globals — allocation-free per harness rules)
__device__ __align__(16) __half g_U[(size_t)NMAX * 512];
__device__ __align__(16) __half g_V[(size_t)NMAX * 512];
__device__ __align__(16) __half g_xA[(size_t)NMAX * 512];
__device__ __align__(16) __half g_xB[(size_t)NMAX * 512];   // also reused as H (fp16)
__device__ __align__(16) __half g_Wt2[256 * 64];
__device__ __align__(16) __half g_Wt3[1024 * 128];
__device__ __align__(16) __half g_Wt4[256 * 512];
__device__ int g_hist[NMAX];
__device__ int g_cursor[NMAX];
__device__ int g_indptr[NMAX + 1];
__device__ int g_csr[EMAX];

// ---------------------------------------------------------------------------
// Helpers
// ---------------------------------------------------------------------------
__device__ __forceinline__ void mma16n8k16_f16(float* d, const uint32_t* a, const uint32_t* b) {
    asm volatile(
        "mma.sync.aligned.m16n8k16.row.col.f32.f16.f16.f32 "
        "{%0,%1,%2,%3}, {%4,%5,%6,%7}, {%8,%9}, {%0,%1,%2,%3};"
        : "+f"(d[0]), "+f"(d[1]), "+f"(d[2]), "+f"(d[3])
        : "r"(a[0]), "r"(a[1]), "r"(a[2]), "r"(a[3]), "r"(b[0]), "r"(b[1]));
}

__device__ __forceinline__ void cpa16(uint32_t dst, const void* src, int szreg) {
    asm volatile("cp.async.cg.shared.global [%0], [%1], 16, %2;"
                 :: "r"(dst), "l"(src), "r"(szreg) : "memory");
}
__device__ __forceinline__ void cpa_commit() {
    asm volatile("cp.async.commit_group;" ::: "memory");
}
template <int NN>
__device__ __forceinline__ void cpa_wait() {
    asm volatile("cp.async.wait_group %0;" :: "n"(NN) : "memory");
}

// ---------------------------------------------------------------------------
// CSR build: histogram -> single-block 2-phase scan -> scatter
// ---------------------------------------------------------------------------
__global__ void zero_int_kernel(int* p, int n) {
    int i = blockIdx.x * blockDim.x + threadIdx.x;
    if (i < n) p[i] = 0;
}

__global__ void hist_kernel(const int* __restrict__ dst, int* __restrict__ hist, int E) {
    int e4 = blockIdx.x * blockDim.x + threadIdx.x;
    int nq = E >> 2;
    if (e4 < nq) {
        int4 d = ((const int4*)dst)[e4];
        atomicAdd(&hist[d.x], 1);
        atomicAdd(&hist[d.y], 1);
        atomicAdd(&hist[d.z], 1);
        atomicAdd(&hist[d.w], 1);
    }
    if (e4 == 0) {
        for (int e = nq << 2; e < E; e++) atomicAdd(&hist[dst[e]], 1);
    }
}

__global__ void scan_kernel(const int* __restrict__ hist, int* __restrict__ indptr,
                            int* __restrict__ cursor, int N) {
    __shared__ int part[1024];
    int tid = threadIdx.x;
    int chunk = (N + 1023) / 1024;
    int lo = tid * chunk;
    int hi = min(lo + chunk, N);

    int s = 0;
    for (int i = lo; i < hi; i++) s += hist[i];
    part[tid] = s;
    __syncthreads();

    #pragma unroll
    for (int off = 1; off < 1024; off <<= 1) {
        int t = (tid >= off) ? part[tid - off] : 0;
        __syncthreads();
        part[tid] += t;
        __syncthreads();
    }
    int run = part[tid] - s;

    for (int i = lo; i < hi; i++) {
        indptr[i] = run;
        cursor[i] = run;
        run += hist[i];
    }
    if (tid == 1023) indptr[N] = part[1023];
}

__global__ void scatter_kernel(const int* __restrict__ src, const int* __restrict__ dst,
                               int* __restrict__ cursor, int* __restrict__ csr, int E) {
    int e4 = blockIdx.x * blockDim.x + threadIdx.x;
    int nq = E >> 2;
    if (e4 < nq) {
        int4 d = ((const int4*)dst)[e4];
        int4 sr = ((const int4*)src)[e4];
        csr[atomicAdd(&cursor[d.x], 1)] = sr.x;
        csr[atomicAdd(&cursor[d.y], 1)] = sr.y;
        csr[atomicAdd(&cursor[d.z], 1)] = sr.z;
        csr[atomicAdd(&cursor[d.w], 1)] = sr.w;
    }
    if (e4 == 0) {
        for (int e = nq << 2; e < E; e++)
            csr[atomicAdd(&cursor[dst[e]], 1)] = src[e];
    }
}

// ---------------------------------------------------------------------------
// Weight pre-transpose (fp32 -> fp16).
// ---------------------------------------------------------------------------
__global__ void build_wt_edge(const float* __restrict__ W, __half* __restrict__ Wt,
                              int K, int Cout) {
    int i = blockIdx.x * blockDim.x + threadIdx.x;
    int total = 2 * Cout * K;
    if (i >= total) return;
    int n = i / K, k = i % K;
    float v;
    if (n < Cout) v = W[k * Cout + n] - W[(k + K) * Cout + n];
    else          v = W[(k + K) * Cout + (n - Cout)];
    Wt[i] = __float2half_rn(v);
}

__global__ void build_wt_lin(const float* __restrict__ W, __half* __restrict__ Wt,
                             int K, int Cout) {
    int i = blockIdx.x * blockDim.x + threadIdx.x;
    int total = Cout * K;
    if (i >= total) return;
    int n = i / K, k = i % K;
    Wt[i] = __float2half_rn(W[k * Cout + n]);
}

// ---------------------------------------------------------------------------
// FP16 mma.sync GEMM with cp.async double-buffering.
//   A  [N x K] fp16, Bt [Ncols x K] fp16 (pre-transposed effective weights)
//   cols [0, Cout_split)            -> outU fp16 (+bias, optional relu)
//   cols [Cout_split, 2*Cout_split) -> outV fp16
// CTA tile 128x128, 8 warps 2(M)x4(N), warp tile 64x32, BK=64 halves, 2 stages.
// ---------------------------------------------------------------------------
#define AST 36
#define AWORDS (128 * AST)
#define STAGE_BYTES (AWORDS * 4)           // 18432
#define GEMM_SMEM (4 * STAGE_BYTES)        // 73728 bytes

__global__ __launch_bounds__(256, 2) void mma_gemm(
    const __half* __restrict__ A, const __half* __restrict__ Bt,
    const float* __restrict__ bias,
    __half* __restrict__ outU, __half* __restrict__ outV,
    int N, int K, int Cout_split, int relu)
{
    extern __shared__ __align__(16) uint32_t dsm[];

    int tid = threadIdx.x;
    int wid = tid >> 5, lane = tid & 31;
    int g = lane >> 2;
    int tg = lane & 3;
    int row0 = blockIdx.y * 128;
    int col0 = blockIdx.x * 128;
    int wm = wid >> 2;
    int wn = wid & 3;

    uint32_t sm_base = (uint32_t)__cvta_generic_to_shared(dsm);

    float acc[4][4][4];
    #pragma unroll
    for (int i = 0; i < 4; i++)
        #pragma unroll
        for (int j = 0; j < 4; j++)
            #pragma unroll
            for (int q = 0; q < 4; q++) acc[i][j][q] = 0.f;

    int nchunk = K >> 6;

    auto load_stage = [&](int buf, int k0) {
        uint32_t aA = sm_base + buf * STAGE_BYTES;
        uint32_t aB = sm_base + 2 * STAGE_BYTES + buf * STAGE_BYTES;
        #pragma unroll
        for (int t = 0; t < 4; t++) {
            int seg = tid + t * 256;
            int row = seg >> 3;
            int off = seg & 7;
            uint32_t soff = (uint32_t)(row * AST + off * 4) * 4u;
            int ga = row0 + row;
            int sz = (ga < N) ? 16 : 0;
            int gac = (ga < N) ? ga : (N - 1);
            cpa16(aA + soff, A + (size_t)gac * K + k0 + off * 8, sz);
            cpa16(aB + soff, Bt + (size_t)(col0 + row) * K + k0 + off * 8, 16);
        }
        cpa_commit();
    };

    load_stage(0, 0);

    for (int c = 0; c < nchunk; c++) {
        if (c + 1 < nchunk) {
            load_stage((c + 1) & 1, (c + 1) << 6);
            cpa_wait<1>();
        } else {
            cpa_wait<0>();
        }
        __syncthreads();

        const uint32_t* sAb = dsm + (c & 1) * AWORDS;
        const uint32_t* sBb = dsm + 2 * AWORDS + (c & 1) * AWORDS;

        #pragma unroll
        for (int s = 0; s < 4; s++) {
            uint32_t af[4][4], bf[4][2];
            #pragma unroll
            for (int i = 0; i < 4; i++) {
                const uint32_t* base = sAb + (wm * 64 + i * 16 + g) * AST + s * 8 + tg;
                af[i][0] = base[0];
                af[i][1] = base[8 * AST];
                af[i][2] = base[4];
                af[i][3] = base[8 * AST + 4];
            }
            #pragma unroll
            for (int j = 0; j < 4; j++) {
                const uint32_t* base = sBb + (wn * 32 + j * 8 + g) * AST + s * 8 + tg;
                bf[j][0] = base[0];
                bf[j][1] = base[4];
            }
            #pragma unroll
            for (int i = 0; i < 4; i++)
                #pragma unroll
                for (int j = 0; j < 4; j++)
                    mma16n8k16_f16(acc[i][j], af[i], bf[j]);
        }
        __syncthreads();
    }

    bool isU = (col0 < Cout_split);
    __half* op = isU ? outU : outV;
    int cbase = isU ? col0 : col0 - Cout_split;

    #pragma unroll
    for (int i = 0; i < 4; i++) {
        int r_lo = row0 + wm * 64 + i * 16 + g;
        int r_hi = r_lo + 8;
        #pragma unroll
        for (int j = 0; j < 4; j++) {
            int gcol = col0 + wn * 32 + j * 8 + tg * 2;
            int ocol = cbase + wn * 32 + j * 8 + tg * 2;
            float2 lo = make_float2(acc[i][j][0], acc[i][j][1]);
            float2 hi = make_float2(acc[i][j][2], acc[i][j][3]);
            if (isU) {
                float b0 = __ldg(&bias[gcol]);
                float b1 = __ldg(&bias[gcol + 1]);
                lo.x += b0; lo.y += b1;
                hi.x += b0; hi.y += b1;
                if (relu) {
                    lo.x = fmaxf(lo.x, 0.f); lo.y = fmaxf(lo.y, 0.f);
                    hi.x = fmaxf(hi.x, 0.f); hi.y = fmaxf(hi.y, 0.f);
                }
            }
            if (r_lo < N) *(__half2*)(op + (size_t)r_lo * Cout_split + ocol) =
                __floats2half2_rn(lo.x, lo.y);
            if (r_hi < N) *(__half2*)(op + (size_t)r_hi * Cout_split + ocol) =
                __floats2half2_rn(hi.x, hi.y);
        }
    }
}

// ---------------------------------------------------------------------------
// SIMT dual GEMM for layer 1 (Cin=3). U/V outputs fp16.
// ---------------------------------------------------------------------------
#define TM 64
#define TN 64
#define BK 16

__global__ __launch_bounds__(256) void dual_gemm(
    const float* __restrict__ x, const float* __restrict__ W,
    const float* __restrict__ bias, __half* __restrict__ U, __half* __restrict__ V,
    int N, int Cin, int Cout)
{
    __shared__ __align__(16) float xs[BK][TM];
    __shared__ __align__(16) float wt[BK][TN];
    __shared__ __align__(16) float wb[BK][TN];
    int tid = threadIdx.x;
    int tx = tid & 15, ty = tid >> 4;
    int row0 = blockIdx.y * TM;
    int col0 = blockIdx.x * TN;

    float acc[4][4] = {};
    float bcc[4][4] = {};

    for (int k0 = 0; k0 < Cin; k0 += BK) {
        #pragma unroll
        for (int i = 0; i < 4; i++) {
            int idx = tid + i * 256;
            int r = idx >> 4, kk = idx & 15;
            int gr = row0 + r, gk = k0 + kk;
            xs[kk][r] = (gr < N && gk < Cin) ? x[gr * Cin + gk] : 0.f;
        }
        #pragma unroll
        for (int i = 0; i < 4; i++) {
            int idx = tid + i * 256;
            int kk = idx >> 6, c = idx & 63;
            int gk = k0 + kk;
            float vt = 0.f, vb = 0.f;
            if (gk < Cin) {
                vt = W[gk * Cout + col0 + c];
                vb = W[(gk + Cin) * Cout + col0 + c];
            }
            wt[kk][c] = vt;
            wb[kk][c] = vb;
        }
        __syncthreads();
        #pragma unroll
        for (int kk = 0; kk < BK; kk++) {
            float4 xv = *(const float4*)(&xs[kk][ty * 4]);
            float4 wtv = *(const float4*)(&wt[kk][tx * 4]);
            float4 wbv = *(const float4*)(&wb[kk][tx * 4]);
            float xr[4] = {xv.x, xv.y, xv.z, xv.w};
            float tr[4] = {wtv.x, wtv.y, wtv.z, wtv.w};
            float br[4] = {wbv.x, wbv.y, wbv.z, wbv.w};
            #pragma unroll
            for (int i = 0; i < 4; i++)
                #pragma unroll
                for (int j = 0; j < 4; j++) {
                    acc[i][j] += xr[i] * tr[j];
                    bcc[i][j] += xr[i] * br[j];
                }
        }
        __syncthreads();
    }

    #pragma unroll
    for (int i = 0; i < 4; i++) {
        int gr = row0 + ty * 4 + i;
        if (gr >= N) continue;
        #pragma unroll
        for (int j = 0; j < 4; j++) {
            int gc = col0 + tx * 4 + j;
            float bv = bcc[i][j];
            U[(size_t)gr * Cout + gc] = __float2half_rn(acc[i][j] - bv + bias[gc]);
            V[(size_t)gr * Cout + gc] = __float2half_rn(bv);
        }
    }
}

// ---------------------------------------------------------------------------
// Fused segment-max (fp16 gather) + relu epilogue, all-fp16 tensors.
// Per-thread unroll-4 form (empirical optimum across R8-R11 variants).
// ---------------------------------------------------------------------------
template <int C>
__global__ __launch_bounds__(256) void aggregate_relu_h(
    const __half* __restrict__ V, const __half* __restrict__ U,
    const int* __restrict__ indptr, const int* __restrict__ csr,
    __half* __restrict__ out, int N)
{
    constexpr int TPN = C / 8;
    int t = blockIdx.x * blockDim.x + threadIdx.x;
    int n = t / TPN;
    int lane = t % TPN;
    if (n >= N) return;

    int beg = indptr[n];
    int end = indptr[n + 1];

    const __half2 NI2 = __halves2half2(__ushort_as_half(0xFC00), __ushort_as_half(0xFC00));
    __half2 m0 = NI2, m1 = NI2, m2 = NI2, m3 = NI2;

    int j = beg;
    for (; j + 3 < end; j += 4) {
        int s0 = csr[j], s1 = csr[j + 1], s2 = csr[j + 2], s3 = csr[j + 3];
        uint4 q0 = *(const uint4*)(V + (size_t)s0 * C + lane * 8);
        uint4 q1 = *(const uint4*)(V + (size_t)s1 * C + lane * 8);
        uint4 q2 = *(const uint4*)(V + (size_t)s2 * C + lane * 8);
        uint4 q3 = *(const uint4*)(V + (size_t)s3 * C + lane * 8);
        m0 = __hmax2(__hmax2(m0, *(__half2*)&q0.x),
                     __hmax2(*(__half2*)&q1.x, __hmax2(*(__half2*)&q2.x, *(__half2*)&q3.x)));
        m1 = __hmax2(__hmax2(m1, *(__half2*)&q0.y),
                     __hmax2(*(__half2*)&q1.y, __hmax2(*(__half2*)&q2.y, *(__half2*)&q3.y)));
        m2 = __hmax2(__hmax2(m2, *(__half2*)&q0.z),
                     __hmax2(*(__half2*)&q1.z, __hmax2(*(__half2*)&q2.z, *(__half2*)&q3.z)));
        m3 = __hmax2(__hmax2(m3, *(__half2*)&q0.w),
                     __hmax2(*(__half2*)&q1.w, __hmax2(*(__half2*)&q2.w, *(__half2*)&q3.w)));
    }
    for (; j < end; j++) {
        int s = csr[j];
        uint4 q = *(const uint4*)(V + (size_t)s * C + lane * 8);
        m0 = __hmax2(m0, *(__half2*)&q.x);
        m1 = __hmax2(m1, *(__half2*)&q.y);
        m2 = __hmax2(m2, *(__half2*)&q.z);
        m3 = __hmax2(m3, *(__half2*)&q.w);
    }

    uint4 uq = *(const uint4*)(U + (size_t)n * C + lane * 8);
    float2 u0 = __half22float2(*(__half2*)&uq.x);
    float2 u1 = __half22float2(*(__half2*)&uq.y);
    float2 u2 = __half22float2(*(__half2*)&uq.z);
    float2 u3 = __half22float2(*(__half2*)&uq.w);
    float2 f0 = __half22float2(m0);
    float2 f1 = __half22float2(m1);
    float2 f2 = __half22float2(m2);
    float2 f3 = __half22float2(m3);

    uint4 o;
    *(__half2*)&o.x = __floats2half2_rn(fmaxf(u0.x + f0.x, 0.f), fmaxf(u0.y + f0.y, 0.f));
    *(__half2*)&o.y = __floats2half2_rn(fmaxf(u1.x + f1.x, 0.f), fmaxf(u1.y + f1.y, 0.f));
    *(__half2*)&o.z = __floats2half2_rn(fmaxf(u2.x + f2.x, 0.f), fmaxf(u2.y + f2.y, 0.f));
    *(__half2*)&o.w = __floats2half2_rn(fmaxf(u3.x + f3.x, 0.f), fmaxf(u3.y + f3.y, 0.f));
    *(uint4*)(out + (size_t)n * C + lane * 8) = o;
}

// ---------------------------------------------------------------------------
// Final: out[n][c] = x[n][c] + b5[c] + sum_k h[n][k] * W5[k][c], c in {0,1,2}
// h is fp16.
// ---------------------------------------------------------------------------
__global__ __launch_bounds__(256) void final_kernel(
    const __half* __restrict__ h, const float* __restrict__ W5,
    const float* __restrict__ b5, const float* __restrict__ x0,
    float* __restrict__ out, int N)
{
    int warp = (blockIdx.x * blockDim.x + threadIdx.x) >> 5;
    int lane = threadIdx.x & 31;
    if (warp >= N) return;
    const __half* hr = h + (size_t)warp * 256;
    float s0 = 0.f, s1 = 0.f, s2 = 0.f;
    #pragma unroll
    for (int i = 0; i < 4; i++) {
        int k = (lane + i * 32) * 2;
        __half2 hv2 = *(const __half2*)(hr + k);
        float2 hv = __half22float2(hv2);
        s0 += hv.x * __ldg(&W5[k * 3 + 0]) + hv.y * __ldg(&W5[(k + 1) * 3 + 0]);
        s1 += hv.x * __ldg(&W5[k * 3 + 1]) + hv.y * __ldg(&W5[(k + 1) * 3 + 1]);
        s2 += hv.x * __ldg(&W5[k * 3 + 2]) + hv.y * __ldg(&W5[(k + 1) * 3 + 2]);
    }
    #pragma unroll
    for (int off = 16; off > 0; off >>= 1) {
        s0 += __shfl_down_sync(0xFFFFFFFFu, s0, off);
        s1 += __shfl_down_sync(0xFFFFFFFFu, s1, off);
        s2 += __shfl_down_sync(0xFFFFFFFFu, s2, off);
    }
    if (lane == 0) {
        out[warp * 3 + 0] = x0[warp * 3 + 0] + b5[0] + s0;
        out[warp * 3 + 1] = x0[warp * 3 + 1] + b5[1] + s1;
        out[warp * 3 + 2] = x0[warp * 3 + 2] + b5[2] + s2;
    }
}

// ---------------------------------------------------------------------------
// One-time stream/event pool (created on the first, uncaptured call so the
// harness's pre-capture memory baseline includes it; never destroyed).
// ---------------------------------------------------------------------------
static cudaStream_t g_s1 = nullptr, g_s2 = nullptr;
static cudaEvent_t g_evRoot = nullptr, g_evCsr = nullptr, g_evWt = nullptr;

extern "C" void kernel_launch(void* const* d_in, const int* in_sizes, int n_in,
                              void* d_out, int out_size)
{
    const float* x  = (const float*)d_in[0];
    const int*   ei = (const int*)d_in[1];
    const float* W1 = (const float*)d_in[2];
    const float* b1 = (const float*)d_in[3];
    const float* W2 = (const float*)d_in[4];
    const float* b2 = (const float*)d_in[5];
    const float* W3 = (const float*)d_in[6];
    const float* b3 = (const float*)d_in[7];
    const float* W4 = (const float*)d_in[8];
    const float* b4 = (const float*)d_in[9];
    const float* W5 = (const float*)d_in[10];
    const float* b5 = (const float*)d_in[11];

    int N = in_sizes[0] / 3;
    int E = in_sizes[1] / 2;
    const int* src = ei;
    const int* dst = ei + E;

    __half *U, *V, *xA, *xB, *Wt2, *Wt3, *Wt4;
    int *hist, *cursor, *indptr, *csr;
    cudaGetSymbolAddress((void**)&U, g_U);
    cudaGetSymbolAddress((void**)&V, g_V);
    cudaGetSymbolAddress((void**)&xA, g_xA);
    cudaGetSymbolAddress((void**)&xB, g_xB);
    cudaGetSymbolAddress((void**)&Wt2, g_Wt2);
    cudaGetSymbolAddress((void**)&Wt3, g_Wt3);
    cudaGetSymbolAddress((void**)&Wt4, g_Wt4);
    cudaGetSymbolAddress((void**)&hist, g_hist);
    cudaGetSymbolAddress((void**)&cursor, g_cursor);
    cudaGetSymbolAddress((void**)&indptr, g_indptr);
    cudaGetSymbolAddress((void**)&csr, g_csr);

    cudaFuncSetAttribute(mma_gemm, cudaFuncAttributeMaxDynamicSharedMemorySize, GEMM_SMEM);

    // One-time pool init (first call = uncaptured correctness run).
    if (!g_s1) {
        cudaStreamCreateWithFlags(&g_s1, cudaStreamNonBlocking);
        cudaStreamCreateWithFlags(&g_s2, cudaStreamNonBlocking);
        cudaEventCreateWithFlags(&g_evRoot, cudaEventDisableTiming);
        cudaEventCreateWithFlags(&g_evCsr, cudaEventDisableTiming);
        cudaEventCreateWithFlags(&g_evWt, cudaEventDisableTiming);
    }

    // Fork side streams off the capture stream.
    cudaEventRecord(g_evRoot, 0);
    cudaStreamWaitEvent(g_s1, g_evRoot, 0);
    cudaStreamWaitEvent(g_s2, g_evRoot, 0);

    // s1: CSR build chain
    zero_int_kernel<<<(N + 255) / 256, 256, 0, g_s1>>>(hist, N);
    hist_kernel<<<(E / 4 + 255) / 256, 256, 0, g_s1>>>(dst, hist, E);
    scan_kernel<<<1, 1024, 0, g_s1>>>(hist, indptr, cursor, N);
    scatter_kernel<<<(E / 4 + 255) / 256, 256, 0, g_s1>>>(src, dst, cursor, csr, E);
    cudaEventRecord(g_evCsr, g_s1);

    // s2: all weight transposes
    build_wt_edge<<<(2 * 128 * 64 + 255) / 256, 256, 0, g_s2>>>(W2, Wt2, 64, 128);
    build_wt_edge<<<(2 * 512 * 128 + 255) / 256, 256, 0, g_s2>>>(W3, Wt3, 128, 512);
    build_wt_lin<<<(256 * 512 + 255) / 256, 256, 0, g_s2>>>(W4, Wt4, 512, 256);
    cudaEventRecord(g_evWt, g_s2);

    // main stream: layer-1 SIMT GEMM (independent of CSR/weights)
    dual_gemm<<<dim3(64 / TN, (N + TM - 1) / TM), 256>>>(x, W1, b1, U, V, N, 3, 64);

    // join
    cudaStreamWaitEvent(0, g_evCsr, 0);
    cudaStreamWaitEvent(0, g_evWt, 0);

    int nrb = (N + 127) / 128;

    aggregate_relu_h<64><<<((size_t)N * 8 + 255) / 256, 256>>>(V, U, indptr, csr, xA, N);

    // Layer 2: Cin=64 -> 128
    mma_gemm<<<dim3(2, nrb), 256, GEMM_SMEM>>>(xA, Wt2, b2, U, V, N, 64, 128, 0);
    aggregate_relu_h<128><<<((size_t)N * 16 + 255) / 256, 256>>>(V, U, indptr, csr, xB, N);

    // Layer 3: Cin=128 -> 512
    mma_gemm<<<dim3(8, nrb), 256, GEMM_SMEM>>>(xB, Wt3, b3, U, V, N, 128, 512, 0);
    aggregate_relu_h<512><<<((size_t)N * 64 + 255) / 256, 256>>>(V, U, indptr, csr, xA, N);

    // lin1: h = relu(x3 @ W4 + b4) -> xB (fp16, reused as H; only U path written)
    mma_gemm<<<dim3(2, nrb), 256, GEMM_SMEM>>>(xA, Wt4, b4, xB, V, N, 512, 256, 1);

    // out = x + (h @ W5 + b5)
    final_kernel<<<((size_t)N * 32 + 255) / 256, 256>>>(xB, W5, b5, x, (float*)d_out, N);
}

// round 14
// speedup vs baseline: 1.0523x; 1.0523x over previous
#include <cuda_runtime.h>
#include <cuda_fp16.h>
#include <math_constants.h>
#include <cstdint>

// Problem-fixed maxima (DGCNN: N=50000 nodes, E=1000000 edges, max width 512)
#define NMAX 50000
#define EMAX 1000000

// Scratch (static __device__ globals — allocation-free per harness rules)
__device__ __align__(16) __half g_U[(size_t)NMAX * 512];
__device__ __align__(16) __half g_V[(size_t)NMAX * 512];
__device__ __align__(16) __half g_xA[(size_t)NMAX * 512];
__device__ __align__(16) __half g_xB[(size_t)NMAX * 512];
__device__ __align__(16) __half g_Wt2[256 * 64];
__device__ __align__(16) __half g_Wt3[1024 * 128];
__device__ __align__(16) __half g_Wt4[256 * 512];
__device__ int g_hist[NMAX];
__device__ int g_cursor[NMAX];
__device__ int g_indptr[NMAX + 1];
__device__ int g_csr[EMAX];

// ---------------------------------------------------------------------------
// Helpers
// ---------------------------------------------------------------------------
__device__ __forceinline__ void mma16n8k16_f16(float* d, const uint32_t* a, const uint32_t* b) {
    asm volatile(
        "mma.sync.aligned.m16n8k16.row.col.f32.f16.f16.f32 "
        "{%0,%1,%2,%3}, {%4,%5,%6,%7}, {%8,%9}, {%0,%1,%2,%3};"
        : "+f"(d[0]), "+f"(d[1]), "+f"(d[2]), "+f"(d[3])
        : "r"(a[0]), "r"(a[1]), "r"(a[2]), "r"(a[3]), "r"(b[0]), "r"(b[1]));
}

__device__ __forceinline__ void cpa16(uint32_t dst, const void* src, int szreg) {
    asm volatile("cp.async.cg.shared.global [%0], [%1], 16, %2;"
                 :: "r"(dst), "l"(src), "r"(szreg) : "memory");
}
__device__ __forceinline__ void cpa_commit() {
    asm volatile("cp.async.commit_group;" ::: "memory");
}
template <int NN>
__device__ __forceinline__ void cpa_wait() {
    asm volatile("cp.async.wait_group %0;" :: "n"(NN) : "memory");
}

// ---------------------------------------------------------------------------
// CSR build: histogram -> single-block 2-phase scan -> scatter
// ---------------------------------------------------------------------------
__global__ void zero_int_kernel(int* p, int n) {
    int i = blockIdx.x * blockDim.x + threadIdx.x;
    if (i < n) p[i] = 0;
}

__global__ void hist_kernel(const int* __restrict__ dst, int* __restrict__ hist, int E) {
    int e4 = blockIdx.x * blockDim.x + threadIdx.x;
    int nq = E >> 2;
    if (e4 < nq) {
        int4 d = ((const int4*)dst)[e4];
        atomicAdd(&hist[d.x], 1);
        atomicAdd(&hist[d.y], 1);
        atomicAdd(&hist[d.z], 1);
        atomicAdd(&hist[d.w], 1);
    }
    if (e4 == 0) {
        for (int e = nq << 2; e < E; e++) atomicAdd(&hist[dst[e]], 1);
    }
}

__global__ void scan_kernel(const int* __restrict__ hist, int* __restrict__ indptr,
                            int* __restrict__ cursor, int N) {
    __shared__ int part[1024];
    int tid = threadIdx.x;
    int chunk = (N + 1023) / 1024;
    int lo = tid * chunk;
    int hi = min(lo + chunk, N);

    int s = 0;
    for (int i = lo; i < hi; i++) s += hist[i];
    part[tid] = s;
    __syncthreads();

    #pragma unroll
    for (int off = 1; off < 1024; off <<= 1) {
        int t = (tid >= off) ? part[tid - off] : 0;
        __syncthreads();
        part[tid] += t;
        __syncthreads();
    }
    int run = part[tid] - s;

    for (int i = lo; i < hi; i++) {
        indptr[i] = run;
        cursor[i] = run;
        run += hist[i];
    }
    if (tid == 1023) indptr[N] = part[1023];
}

__global__ void scatter_kernel(const int* __restrict__ src, const int* __restrict__ dst,
                               int* __restrict__ cursor, int* __restrict__ csr, int E) {
    int e4 = blockIdx.x * blockDim.x + threadIdx.x;
    int nq = E >> 2;
    if (e4 < nq) {
        int4 d = ((const int4*)dst)[e4];
        int4 sr = ((const int4*)src)[e4];
        csr[atomicAdd(&cursor[d.x], 1)] = sr.x;
        csr[atomicAdd(&cursor[d.y], 1)] = sr.y;
        csr[atomicAdd(&cursor[d.z], 1)] = sr.z;
        csr[atomicAdd(&cursor[d.w], 1)] = sr.w;
    }
    if (e4 == 0) {
        for (int e = nq << 2; e < E; e++)
            csr[atomicAdd(&cursor[dst[e]], 1)] = src[e];
    }
}

// ---------------------------------------------------------------------------
// Weight pre-transpose (fp32 -> fp16).
// ---------------------------------------------------------------------------
__global__ void build_wt_edge(const float* __restrict__ W, __half* __restrict__ Wt,
                              int K, int Cout) {
    int i = blockIdx.x * blockDim.x + threadIdx.x;
    int total = 2 * Cout * K;
    if (i >= total) return;
    int n = i / K, k = i % K;
    float v;
    if (n < Cout) v = W[k * Cout + n] - W[(k + K) * Cout + n];
    else          v = W[(k + K) * Cout + (n - Cout)];
    Wt[i] = __float2half_rn(v);
}

__global__ void build_wt_lin(const float* __restrict__ W, __half* __restrict__ Wt,
                             int K, int Cout) {
    int i = blockIdx.x * blockDim.x + threadIdx.x;
    int total = Cout * K;
    if (i >= total) return;
    int n = i / K, k = i % K;
    Wt[i] = __float2half_rn(W[k * Cout + n]);
}

// out[n][c] = x[n][c] + b5[c]  (seed for the fused-final atomic accumulation)
__global__ void init_out(const float* __restrict__ x0, const float* __restrict__ b5,
                         float* __restrict__ out, int N) {
    int i = blockIdx.x * blockDim.x + threadIdx.x;
    if (i < N * 3) out[i] = x0[i] + __ldg(&b5[i % 3]);
}

// ---------------------------------------------------------------------------
// FP16 mma.sync GEMM with cp.async double-buffering.
//   A  [N x K] fp16, Bt [Ncols x K] fp16 (pre-transposed effective weights)
//   cols [0, Cout_split)            -> outU fp16 (+bias, optional relu)
//   cols [Cout_split, 2*Cout_split) -> outV fp16
// If ff != 0 (fused final): h = relu(acc+bias) stays in registers; partial
// GEMV against W5f [Ncols x 3] is reduced across tg lanes and atomicAdd-ed
// into outF (pre-seeded with x + b5). No fp16 h is materialized.
// CTA tile 128x128, 8 warps 2(M)x4(N), warp tile 64x32, BK=64 halves, 2 stages.
// ---------------------------------------------------------------------------
#define AST 36
#define AWORDS (128 * AST)
#define STAGE_BYTES (AWORDS * 4)           // 18432
#define GEMM_SMEM (4 * STAGE_BYTES)        // 73728 bytes

__global__ __launch_bounds__(256, 2) void mma_gemm(
    const __half* __restrict__ A, const __half* __restrict__ Bt,
    const float* __restrict__ bias,
    __half* __restrict__ outU, __half* __restrict__ outV,
    int N, int K, int Cout_split, int relu,
    const float* __restrict__ W5f, float* __restrict__ outF, int ff)
{
    extern __shared__ __align__(16) uint32_t dsm[];

    int tid = threadIdx.x;
    int wid = tid >> 5, lane = tid & 31;
    int g = lane >> 2;
    int tg = lane & 3;
    int row0 = blockIdx.y * 128;
    int col0 = blockIdx.x * 128;
    int wm = wid >> 2;
    int wn = wid & 3;

    uint32_t sm_base = (uint32_t)__cvta_generic_to_shared(dsm);

    float acc[4][4][4];
    #pragma unroll
    for (int i = 0; i < 4; i++)
        #pragma unroll
        for (int j = 0; j < 4; j++)
            #pragma unroll
            for (int q = 0; q < 4; q++) acc[i][j][q] = 0.f;

    int nchunk = K >> 6;

    auto load_stage = [&](int buf, int k0) {
        uint32_t aA = sm_base + buf * STAGE_BYTES;
        uint32_t aB = sm_base + 2 * STAGE_BYTES + buf * STAGE_BYTES;
        #pragma unroll
        for (int t = 0; t < 4; t++) {
            int seg = tid + t * 256;
            int row = seg >> 3;
            int off = seg & 7;
            uint32_t soff = (uint32_t)(row * AST + off * 4) * 4u;
            int ga = row0 + row;
            int sz = (ga < N) ? 16 : 0;
            int gac = (ga < N) ? ga : (N - 1);
            cpa16(aA + soff, A + (size_t)gac * K + k0 + off * 8, sz);
            cpa16(aB + soff, Bt + (size_t)(col0 + row) * K + k0 + off * 8, 16);
        }
        cpa_commit();
    };

    load_stage(0, 0);

    for (int c = 0; c < nchunk; c++) {
        if (c + 1 < nchunk) {
            load_stage((c + 1) & 1, (c + 1) << 6);
            cpa_wait<1>();
        } else {
            cpa_wait<0>();
        }
        __syncthreads();

        const uint32_t* sAb = dsm + (c & 1) * AWORDS;
        const uint32_t* sBb = dsm + 2 * AWORDS + (c & 1) * AWORDS;

        #pragma unroll
        for (int s = 0; s < 4; s++) {
            uint32_t af[4][4], bf[4][2];
            #pragma unroll
            for (int i = 0; i < 4; i++) {
                const uint32_t* base = sAb + (wm * 64 + i * 16 + g) * AST + s * 8 + tg;
                af[i][0] = base[0];
                af[i][1] = base[8 * AST];
                af[i][2] = base[4];
                af[i][3] = base[8 * AST + 4];
            }
            #pragma unroll
            for (int j = 0; j < 4; j++) {
                const uint32_t* base = sBb + (wn * 32 + j * 8 + g) * AST + s * 8 + tg;
                bf[j][0] = base[0];
                bf[j][1] = base[4];
            }
            #pragma unroll
            for (int i = 0; i < 4; i++)
                #pragma unroll
                for (int j = 0; j < 4; j++)
                    mma16n8k16_f16(acc[i][j], af[i], bf[j]);
        }
        __syncthreads();
    }

    if (ff) {
        // Fused final: h = relu(acc + bias); p[i][r][c] = per-row partial GEMV.
        float p[4][2][3];
        #pragma unroll
        for (int i = 0; i < 4; i++)
            #pragma unroll
            for (int r = 0; r < 2; r++)
                #pragma unroll
                for (int c = 0; c < 3; c++) p[i][r][c] = 0.f;

        #pragma unroll
        for (int i = 0; i < 4; i++) {
            #pragma unroll
            for (int j = 0; j < 4; j++) {
                int gcol = col0 + wn * 32 + j * 8 + tg * 2;
                float b0 = __ldg(&bias[gcol]);
                float b1 = __ldg(&bias[gcol + 1]);
                float h00 = fmaxf(acc[i][j][0] + b0, 0.f);
                float h01 = fmaxf(acc[i][j][1] + b1, 0.f);
                float h10 = fmaxf(acc[i][j][2] + b0, 0.f);
                float h11 = fmaxf(acc[i][j][3] + b1, 0.f);
                #pragma unroll
                for (int c = 0; c < 3; c++) {
                    float w0 = __ldg(&W5f[gcol * 3 + c]);
                    float w1 = __ldg(&W5f[(gcol + 1) * 3 + c]);
                    p[i][0][c] += h00 * w0 + h01 * w1;
                    p[i][1][c] += h10 * w0 + h11 * w1;
                }
            }
        }
        // Reduce across the 4 tg lanes (consecutive lanes share g -> width 4).
        #pragma unroll
        for (int i = 0; i < 4; i++)
            #pragma unroll
            for (int r = 0; r < 2; r++)
                #pragma unroll
                for (int c = 0; c < 3; c++) {
                    float v = p[i][r][c];
                    v += __shfl_down_sync(0xFFFFFFFFu, v, 2, 4);
                    v += __shfl_down_sync(0xFFFFFFFFu, v, 1, 4);
                    p[i][r][c] = v;
                }
        if (tg == 0) {
            #pragma unroll
            for (int i = 0; i < 4; i++) {
                int r_lo = row0 + wm * 64 + i * 16 + g;
                int r_hi = r_lo + 8;
                if (r_lo < N) {
                    atomicAdd(&outF[r_lo * 3 + 0], p[i][0][0]);
                    atomicAdd(&outF[r_lo * 3 + 1], p[i][0][1]);
                    atomicAdd(&outF[r_lo * 3 + 2], p[i][0][2]);
                }
                if (r_hi < N) {
                    atomicAdd(&outF[r_hi * 3 + 0], p[i][1][0]);
                    atomicAdd(&outF[r_hi * 3 + 1], p[i][1][1]);
                    atomicAdd(&outF[r_hi * 3 + 2], p[i][1][2]);
                }
            }
        }
        return;
    }

    bool isU = (col0 < Cout_split);
    __half* op = isU ? outU : outV;
    int cbase = isU ? col0 : col0 - Cout_split;

    #pragma unroll
    for (int i = 0; i < 4; i++) {
        int r_lo = row0 + wm * 64 + i * 16 + g;
        int r_hi = r_lo + 8;
        #pragma unroll
        for (int j = 0; j < 4; j++) {
            int gcol = col0 + wn * 32 + j * 8 + tg * 2;
            int ocol = cbase + wn * 32 + j * 8 + tg * 2;
            float2 lo = make_float2(acc[i][j][0], acc[i][j][1]);
            float2 hi = make_float2(acc[i][j][2], acc[i][j][3]);
            if (isU) {
                float b0 = __ldg(&bias[gcol]);
                float b1 = __ldg(&bias[gcol + 1]);
                lo.x += b0; lo.y += b1;
                hi.x += b0; hi.y += b1;
                if (relu) {
                    lo.x = fmaxf(lo.x, 0.f); lo.y = fmaxf(lo.y, 0.f);
                    hi.x = fmaxf(hi.x, 0.f); hi.y = fmaxf(hi.y, 0.f);
                }
            }
            if (r_lo < N) *(__half2*)(op + (size_t)r_lo * Cout_split + ocol) =
                __floats2half2_rn(lo.x, lo.y);
            if (r_hi < N) *(__half2*)(op + (size_t)r_hi * Cout_split + ocol) =
                __floats2half2_rn(hi.x, hi.y);
        }
    }
}

// ---------------------------------------------------------------------------
// SIMT dual GEMM for layer 1 (Cin=3). U/V outputs fp16.
// ---------------------------------------------------------------------------
#define TM 64
#define TN 64
#define BK 16

__global__ __launch_bounds__(256) void dual_gemm(
    const float* __restrict__ x, const float* __restrict__ W,
    const float* __restrict__ bias, __half* __restrict__ U, __half* __restrict__ V,
    int N, int Cin, int Cout)
{
    __shared__ __align__(16) float xs[BK][TM];
    __shared__ __align__(16) float wt[BK][TN];
    __shared__ __align__(16) float wb[BK][TN];
    int tid = threadIdx.x;
    int tx = tid & 15, ty = tid >> 4;
    int row0 = blockIdx.y * TM;
    int col0 = blockIdx.x * TN;

    float acc[4][4] = {};
    float bcc[4][4] = {};

    for (int k0 = 0; k0 < Cin; k0 += BK) {
        #pragma unroll
        for (int i = 0; i < 4; i++) {
            int idx = tid + i * 256;
            int r = idx >> 4, kk = idx & 15;
            int gr = row0 + r, gk = k0 + kk;
            xs[kk][r] = (gr < N && gk < Cin) ? x[gr * Cin + gk] : 0.f;
        }
        #pragma unroll
        for (int i = 0; i < 4; i++) {
            int idx = tid + i * 256;
            int kk = idx >> 6, c = idx & 63;
            int gk = k0 + kk;
            float vt = 0.f, vb = 0.f;
            if (gk < Cin) {
                vt = W[gk * Cout + col0 + c];
                vb = W[(gk + Cin) * Cout + col0 + c];
            }
            wt[kk][c] = vt;
            wb[kk][c] = vb;
        }
        __syncthreads();
        #pragma unroll
        for (int kk = 0; kk < BK; kk++) {
            float4 xv = *(const float4*)(&xs[kk][ty * 4]);
            float4 wtv = *(const float4*)(&wt[kk][tx * 4]);
            float4 wbv = *(const float4*)(&wb[kk][tx * 4]);
            float xr[4] = {xv.x, xv.y, xv.z, xv.w};
            float tr[4] = {wtv.x, wtv.y, wtv.z, wtv.w};
            float br[4] = {wbv.x, wbv.y, wbv.z, wbv.w};
            #pragma unroll
            for (int i = 0; i < 4; i++)
                #pragma unroll
                for (int j = 0; j < 4; j++) {
                    acc[i][j] += xr[i] * tr[j];
                    bcc[i][j] += xr[i] * br[j];
                }
        }
        __syncthreads();
    }

    #pragma unroll
    for (int i = 0; i < 4; i++) {
        int gr = row0 + ty * 4 + i;
        if (gr >= N) continue;
        #pragma unroll
        for (int j = 0; j < 4; j++) {
            int gc = col0 + tx * 4 + j;
            float bv = bcc[i][j];
            U[(size_t)gr * Cout + gc] = __float2half_rn(acc[i][j] - bv + bias[gc]);
            V[(size_t)gr * Cout + gc] = __float2half_rn(bv);
        }
    }
}

// ---------------------------------------------------------------------------
// Fused segment-max (fp16 gather) + relu epilogue, all-fp16 tensors.
// Per-thread unroll-4 form (empirical optimum across R8-R11 variants).
// ---------------------------------------------------------------------------
template <int C>
__global__ __launch_bounds__(256) void aggregate_relu_h(
    const __half* __restrict__ V, const __half* __restrict__ U,
    const int* __restrict__ indptr, const int* __restrict__ csr,
    __half* __restrict__ out, int N)
{
    constexpr int TPN = C / 8;
    int t = blockIdx.x * blockDim.x + threadIdx.x;
    int n = t / TPN;
    int lane = t % TPN;
    if (n >= N) return;

    int beg = indptr[n];
    int end = indptr[n + 1];

    const __half2 NI2 = __halves2half2(__ushort_as_half(0xFC00), __ushort_as_half(0xFC00));
    __half2 m0 = NI2, m1 = NI2, m2 = NI2, m3 = NI2;

    int j = beg;
    for (; j + 3 < end; j += 4) {
        int s0 = csr[j], s1 = csr[j + 1], s2 = csr[j + 2], s3 = csr[j + 3];
        uint4 q0 = *(const uint4*)(V + (size_t)s0 * C + lane * 8);
        uint4 q1 = *(const uint4*)(V + (size_t)s1 * C + lane * 8);
        uint4 q2 = *(const uint4*)(V + (size_t)s2 * C + lane * 8);
        uint4 q3 = *(const uint4*)(V + (size_t)s3 * C + lane * 8);
        m0 = __hmax2(__hmax2(m0, *(__half2*)&q0.x),
                     __hmax2(*(__half2*)&q1.x, __hmax2(*(__half2*)&q2.x, *(__half2*)&q3.x)));
        m1 = __hmax2(__hmax2(m1, *(__half2*)&q0.y),
                     __hmax2(*(__half2*)&q1.y, __hmax2(*(__half2*)&q2.y, *(__half2*)&q3.y)));
        m2 = __hmax2(__hmax2(m2, *(__half2*)&q0.z),
                     __hmax2(*(__half2*)&q1.z, __hmax2(*(__half2*)&q2.z, *(__half2*)&q3.z)));
        m3 = __hmax2(__hmax2(m3, *(__half2*)&q0.w),
                     __hmax2(*(__half2*)&q1.w, __hmax2(*(__half2*)&q2.w, *(__half2*)&q3.w)));
    }
    for (; j < end; j++) {
        int s = csr[j];
        uint4 q = *(const uint4*)(V + (size_t)s * C + lane * 8);
        m0 = __hmax2(m0, *(__half2*)&q.x);
        m1 = __hmax2(m1, *(__half2*)&q.y);
        m2 = __hmax2(m2, *(__half2*)&q.z);
        m3 = __hmax2(m3, *(__half2*)&q.w);
    }

    uint4 uq = *(const uint4*)(U + (size_t)n * C + lane * 8);
    float2 u0 = __half22float2(*(__half2*)&uq.x);
    float2 u1 = __half22float2(*(__half2*)&uq.y);
    float2 u2 = __half22float2(*(__half2*)&uq.z);
    float2 u3 = __half22float2(*(__half2*)&uq.w);
    float2 f0 = __half22float2(m0);
    float2 f1 = __half22float2(m1);
    float2 f2 = __half22float2(m2);
    float2 f3 = __half22float2(m3);

    uint4 o;
    *(__half2*)&o.x = __floats2half2_rn(fmaxf(u0.x + f0.x, 0.f), fmaxf(u0.y + f0.y, 0.f));
    *(__half2*)&o.y = __floats2half2_rn(fmaxf(u1.x + f1.x, 0.f), fmaxf(u1.y + f1.y, 0.f));
    *(__half2*)&o.z = __floats2half2_rn(fmaxf(u2.x + f2.x, 0.f), fmaxf(u2.y + f2.y, 0.f));
    *(__half2*)&o.w = __floats2half2_rn(fmaxf(u3.x + f3.x, 0.f), fmaxf(u3.y + f3.y, 0.f));
    *(uint4*)(out + (size_t)n * C + lane * 8) = o;
}

// ---------------------------------------------------------------------------
// One-time stream/event pool (created on the first, uncaptured call so the
// harness's pre-capture memory baseline includes it; never destroyed).
// ---------------------------------------------------------------------------
static cudaStream_t g_s1 = nullptr, g_s2 = nullptr;
static cudaEvent_t g_evRoot = nullptr, g_evCsr = nullptr, g_evWt = nullptr;

extern "C" void kernel_launch(void* const* d_in, const int* in_sizes, int n_in,
                              void* d_out, int out_size)
{
    const float* x  = (const float*)d_in[0];
    const int*   ei = (const int*)d_in[1];
    const float* W1 = (const float*)d_in[2];
    const float* b1 = (const float*)d_in[3];
    const float* W2 = (const float*)d_in[4];
    const float* b2 = (const float*)d_in[5];
    const float* W3 = (const float*)d_in[6];
    const float* b3 = (const float*)d_in[7];
    const float* W4 = (const float*)d_in[8];
    const float* b4 = (const float*)d_in[9];
    const float* W5 = (const float*)d_in[10];
    const float* b5 = (const float*)d_in[11];

    int N = in_sizes[0] / 3;
    int E = in_sizes[1] / 2;
    const int* src = ei;
    const int* dst = ei + E;

    __half *U, *V, *xA, *xB, *Wt2, *Wt3, *Wt4;
    int *hist, *cursor, *indptr, *csr;
    cudaGetSymbolAddress((void**)&U, g_U);
    cudaGetSymbolAddress((void**)&V, g_V);
    cudaGetSymbolAddress((void**)&xA, g_xA);
    cudaGetSymbolAddress((void**)&xB, g_xB);
    cudaGetSymbolAddress((void**)&Wt2, g_Wt2);
    cudaGetSymbolAddress((void**)&Wt3, g_Wt3);
    cudaGetSymbolAddress((void**)&Wt4, g_Wt4);
    cudaGetSymbolAddress((void**)&hist, g_hist);
    cudaGetSymbolAddress((void**)&cursor, g_cursor);
    cudaGetSymbolAddress((void**)&indptr, g_indptr);
    cudaGetSymbolAddress((void**)&csr, g_csr);

    cudaFuncSetAttribute(mma_gemm, cudaFuncAttributeMaxDynamicSharedMemorySize, GEMM_SMEM);

    // One-time pool init (first call = uncaptured correctness run).
    if (!g_s1) {
        cudaStreamCreateWithFlags(&g_s1, cudaStreamNonBlocking);
        cudaStreamCreateWithFlags(&g_s2, cudaStreamNonBlocking);
        cudaEventCreateWithFlags(&g_evRoot, cudaEventDisableTiming);
        cudaEventCreateWithFlags(&g_evCsr, cudaEventDisableTiming);
        cudaEventCreateWithFlags(&g_evWt, cudaEventDisableTiming);
    }

    // Fork side streams off the capture stream.
    cudaEventRecord(g_evRoot, 0);
    cudaStreamWaitEvent(g_s1, g_evRoot, 0);
    cudaStreamWaitEvent(g_s2, g_evRoot, 0);

    // s1: CSR build chain
    zero_int_kernel<<<(N + 255) / 256, 256, 0, g_s1>>>(hist, N);
    hist_kernel<<<(E / 4 + 255) / 256, 256, 0, g_s1>>>(dst, hist, E);
    scan_kernel<<<1, 1024, 0, g_s1>>>(hist, indptr, cursor, N);
    scatter_kernel<<<(E / 4 + 255) / 256, 256, 0, g_s1>>>(src, dst, cursor, csr, E);
    cudaEventRecord(g_evCsr, g_s1);

    // s2: all weight transposes
    build_wt_edge<<<(2 * 128 * 64 + 255) / 256, 256, 0, g_s2>>>(W2, Wt2, 64, 128);
    build_wt_edge<<<(2 * 512 * 128 + 255) / 256, 256, 0, g_s2>>>(W3, Wt3, 128, 512);
    build_wt_lin<<<(256 * 512 + 255) / 256, 256, 0, g_s2>>>(W4, Wt4, 512, 256);
    cudaEventRecord(g_evWt, g_s2);

    // main stream: layer-1 SIMT GEMM (independent of CSR/weights)
    dual_gemm<<<dim3(64 / TN, (N + TM - 1) / TM), 256>>>(x, W1, b1, U, V, N, 3, 64);

    // join
    cudaStreamWaitEvent(0, g_evCsr, 0);
    cudaStreamWaitEvent(0, g_evWt, 0);

    int nrb = (N + 127) / 128;

    aggregate_relu_h<64><<<((size_t)N * 8 + 255) / 256, 256>>>(V, U, indptr, csr, xA, N);

    // Layer 2: Cin=64 -> 128
    mma_gemm<<<dim3(2, nrb), 256, GEMM_SMEM>>>(xA, Wt2, b2, U, V, N, 64, 128, 0,
                                               nullptr, nullptr, 0);
    aggregate_relu_h<128><<<((size_t)N * 16 + 255) / 256, 256>>>(V, U, indptr, csr, xB, N);

    // Layer 3: Cin=128 -> 512
    mma_gemm<<<dim3(8, nrb), 256, GEMM_SMEM>>>(xB, Wt3, b3, U, V, N, 128, 512, 0,
                                               nullptr, nullptr, 0);
    aggregate_relu_h<512><<<((size_t)N * 64 + 255) / 256, 256>>>(V, U, indptr, csr, xA, N);

    // Fused lin1 + final: seed out = x + b5, then GEMM atomically adds h@W5.
    init_out<<<((size_t)N * 3 + 255) / 256, 256>>>(x, b5, (float*)d_out, N);
    mma_gemm<<<dim3(2, nrb), 256, GEMM_SMEM>>>(xA, Wt4, b4, xB, V, N, 512, 256, 1,
                                               W5, (float*)d_out, 1);
}